// round 12
// baseline (speedup 1.0000x reference)
#include <cuda_runtime.h>

#define BB 64
#define CC 256
#define HH 56
#define WW 56
#define SH 52
#define SW 52
#define NPLANES (BB*CC)                 // 16384
#define SEEDS_PER_PLANE (SH*SW)         // 2704
#define OUT_PER_PLANE (HH*WW)           // 3136
#define COUNT_M 51380224                // NPLANES * OUT_PER_PLANE
#define TOTAL_F4 (COUNT_M/4)            // 12845056

#define P 8                             // planes per block = warps per block
#define F4PP (SEEDS_PER_PLANE/4)        // 676 float4 per plane
#define NBLK1 (NPLANES/P)               // 2048 dilate blocks
#define NBLK3 (TOTAL_F4/1024)           // 12544 apply blocks

// Scratch (no allocations allowed).
__device__ unsigned long long g_dmask[NPLANES * HH];   // 56 row bitmasks/plane -> 7.3 MB
__device__ unsigned int       g_total  = 0;            // dropped-count accumulator
__device__ unsigned int       g_ticket = 0;            // apply-block arrival ticket
                                                       // (atomicInc wrap -> 0 each replay)

// Pack 4 bytes (each holding a 4-bit value in its low nibble) into 16 bits.
__device__ __forceinline__ unsigned pack16(unsigned w) {
    unsigned t = w | (w >> 4);
    t &= 0x00FF00FFu;
    return (t | (t >> 8)) & 0xFFFFu;
}

// ---------------------------------------------------------------------------
// Kernel 1 (measured 32.0us): fully warp-synchronous, one plane per warp,
// zero __syncthreads. Loads batched 2x11 float4 for deep MLP. Per-warp
// dropped count via ONE plain atomicAdd -- no fences (gpu-scope fences emit
// CCTL.IVALL on sm_103a and flush L1, measured -7us regression in R7).
// ---------------------------------------------------------------------------
__global__ void __launch_bounds__(256, 3) dilate_kernel(const float4* __restrict__ u4,
                                                        const float* __restrict__ gammap) {
    __shared__ unsigned char      nib[P][SH][16];   // 13 nibbles/row, 16B rows
    __shared__ unsigned long long rowd[P][SH];      // horizontally-dilated rows

    const int warp = threadIdx.x >> 5;
    const int lane = threadIdx.x & 31;
    const int plane = blockIdx.x * P + warp;
    const float gamma = __ldg(gammap);
    const float4* up = u4 + (size_t)plane * F4PP;

    // Two batches of 11 float4s: issue all loads, then threshold + byte-store.
    #pragma unroll
    for (int b = 0; b < 2; b++) {
        float4 v[11];
        #pragma unroll
        for (int j = 0; j < 11; j++) {
            int f = 32 * (11 * b + j) + lane;
            if (f < F4PP) v[j] = __ldcs(&up[f]);
        }
        #pragma unroll
        for (int j = 0; j < 11; j++) {
            int f = 32 * (11 * b + j) + lane;
            if (f < F4PP) {
                unsigned n = (unsigned)(v[j].x < gamma)
                           | ((unsigned)(v[j].y < gamma) << 1)
                           | ((unsigned)(v[j].z < gamma) << 2)
                           | ((unsigned)(v[j].w < gamma) << 3);
                int row = f / 13;
                int cg  = f - row * 13;
                nib[warp][row][cg] = (unsigned char)n;
            }
        }
    }
    __syncwarp();

    // Horizontal dilation: one LDS.128 per row, nibble-pack to 52 bits,
    // then bit j = OR of seed bits [j-4, j].
    for (int r = lane; r < SH; r += 32) {
        uint4 w = *(const uint4*)&nib[warp][r][0];
        unsigned long long rr =
              (unsigned long long)(pack16(w.x) | (pack16(w.y) << 16))
            | ((unsigned long long)(pack16(w.z) | (pack16(w.w) << 16)) << 32);
        rr &= 0x000FFFFFFFFFFFFFull;     // 52 valid seed bits
        unsigned long long t = rr | (rr << 1);
        t |= (t << 2);
        rr = t | (rr << 4);
        rowd[warp][r] = rr;
    }
    __syncwarp();

    // Vertical dilation: output row i = OR of rows [max(0,i-4), min(51,i)].
    unsigned cnt = 0;
    for (int i = lane; i < HH; i += 32) {
        int lo = i - 4; if (lo < 0) lo = 0;
        int hi = i;     if (hi > SH - 1) hi = SH - 1;
        unsigned long long d = 0;
        for (int p = lo; p <= hi; p++) d |= rowd[warp][p];
        g_dmask[(size_t)plane * HH + i] = d;
        cnt += __popcll(d);
    }

    // Warp-reduce then one fire-and-forget atomic per warp.
    #pragma unroll
    for (int o = 16; o; o >>= 1) cnt += __shfl_down_sync(0xffffffffu, cnt, o);
    if (lane == 0) atomicAdd(&g_total, cnt);
}

// ---------------------------------------------------------------------------
// Kernel 2 (measured 59.8us body): apply, ILP-4. Computes the normalization
// scale in its prologue (count is final at the kernel boundary); the LAST
// block to finish resets g_total for the next graph replay. Each block's
// read of g_total completes (consumed into smem before __syncthreads) before
// its own ticket increment, so the reset -- gated on ALL tickets -- can
// never precede any read. No fences.
// ---------------------------------------------------------------------------
__device__ __forceinline__ void apply_one(const float* __restrict__ x,
                                          float* __restrict__ out,
                                          unsigned f, float s) {
    unsigned plane = f / 784u;                         // 784 f4 per plane
    unsigned rem   = f - plane * 784u;
    unsigned row   = rem / 14u;                        // 14 f4 per 56-wide row
    unsigned cg    = rem - row * 14u;

    const unsigned* dm32 = (const unsigned*)g_dmask;
    unsigned word  = dm32[((size_t)plane * HH + row) * 2 + (cg >> 3)];
    unsigned bits  = (word >> ((cg & 7u) * 4u)) & 0xFu;

    float4 v = __ldcs((const float4*)x + f);
    float4 o;
    o.x = (bits & 1u) ? 0.0f : v.x * s;
    o.y = (bits & 2u) ? 0.0f : v.y * s;
    o.z = (bits & 4u) ? 0.0f : v.z * s;
    o.w = (bits & 8u) ? 0.0f : v.w * s;
    __stcs((float4*)out + f, o);
}

__global__ void __launch_bounds__(256) apply_kernel(const float* __restrict__ x,
                                                    float* __restrict__ out) {
    __shared__ float s_scale;
    if (threadIdx.x == 0) {
        unsigned tot = atomicAdd(&g_total, 0u);        // L2-coherent read
        double ones = (double)COUNT_M - (double)tot;   // kept elements
        s_scale = (float)((double)COUNT_M / (ones + 1e-12));
    }
    __syncthreads();
    const float s = s_scale;

    unsigned base = blockIdx.x * 1024u + threadIdx.x;
    apply_one(x, out, base,        s);
    apply_one(x, out, base + 256u, s);
    apply_one(x, out, base + 512u, s);
    apply_one(x, out, base + 768u, s);

    // Last-arriving block resets the accumulator (replay invariant).
    if (threadIdx.x == 0) {
        unsigned t = atomicInc(&g_ticket, NBLK3 - 1);  // wraps to 0 on last
        if (t == NBLK3 - 1) atomicExch(&g_total, 0u);
    }
}

// ---------------------------------------------------------------------------
extern "C" void kernel_launch(void* const* d_in, const int* in_sizes, int n_in,
                              void* d_out, int out_size) {
    const float* x = nullptr;
    const float* u = nullptr;
    const float* g = nullptr;
    for (int i = 0; i < n_in; i++) {
        if (in_sizes[i] == COUNT_M)                        x = (const float*)d_in[i];
        else if (in_sizes[i] == NPLANES * SEEDS_PER_PLANE) u = (const float*)d_in[i];
        else if (in_sizes[i] == 1)                         g = (const float*)d_in[i];
    }
    float* out = (float*)d_out;

    dilate_kernel<<<NBLK1, 256>>>((const float4*)u, g);
    apply_kernel<<<NBLK3, 256>>>(x, out);
}